// round 16
// baseline (speedup 1.0000x reference)
#include <cuda_runtime.h>
#include <cuda_bf16.h>
#include <cstdint>
#include <cstddef>

// Node2GraphAttention:
//   coef[i] = sigmoid( dot(n_emb[i], g_emb[batch[i]]) )
//   out[g]  = sum_{i: batch[i]==g} coef[i] * n_emb[i]
// n_batch SORTED (avg segment = 50 nodes). Best config (R15: 47.6us, 73% DRAM):
//   - warp-local register accumulation per segment, red.global.add.v4.f32
//     only at segment boundaries / span edges
//   - g row CACHED in registers, reloaded only on segment change
//   - n rows staged through SMEM via cp.async (evict-first), 4-deep ring,
//     wait_group 3; 96-thread blocks, 9/SM: 27 warps x 6KB = 162KB in flight
//   - barrier-free: each lane consumes only the 16B it copied
//   - init via cudaMemsetAsync; int64-detection in-kernel
// R16 deltas: mainloop unrolled x4 (ring slot constant-folded), explicit
// register reuse of the node rows between dot and accumulate, streaming
// index loads.

#define D 128
#define D4 (D / 4)            // 32 float4 per row -> one float4 per lane
#define GROUP 4               // nodes per pipeline group
#define STAGES 4              // smem quad buffer (3 groups in flight)
#define THREADS 96
#define WARPS_PER_BLOCK (THREADS / 32)
#define MIN_BLOCKS 9          // 9 x (24KB + ovh) <= 228KB/SM

__device__ __forceinline__ int load_batch(const void* __restrict__ nb, int i, int is64) {
    if (is64) return (int)__ldcs(&((const long long*)nb)[i]);
    return __ldcs(&((const int*)nb)[i]);
}

__device__ __forceinline__ float sigmoidf_(float x) {
    return 1.0f / (1.0f + __expf(-x));
}

__device__ __forceinline__ float dot4(const float4& a, const float4& b) {
    return a.x * b.x + a.y * b.y + a.z * b.z + a.w * b.w;
}

// One vector reduction instruction per lane (sm_90+), no return value.
__device__ __forceinline__ void flush_seg(float* __restrict__ out, int b, int lane,
                                          const float4& acc) {
    float* p = out + b * D + lane * 4;   // 16B aligned
    asm volatile("red.global.add.v4.f32 [%0], {%1, %2, %3, %4};"
                 :: "l"(p), "f"(acc.x), "f"(acc.y), "f"(acc.z), "f"(acc.w)
                 : "memory");
}

__device__ __forceinline__ void acc_add(float4& acc, float c, const float4& nv) {
    acc.x += c * nv.x;
    acc.y += c * nv.y;
    acc.z += c * nv.z;
    acc.w += c * nv.w;
}

__device__ __forceinline__ unsigned long long mk_policy_ef() {
    unsigned long long pol;
    asm volatile("createpolicy.fractional.L2::evict_first.b64 %0, 1.0;" : "=l"(pol));
    return pol;
}

// n-stream cp.async, evict-first: use-once data must not evict out/g lines.
__device__ __forceinline__ void cp16(float4* dst_smem, const float4* __restrict__ src,
                                     unsigned long long pol) {
    unsigned saddr = (unsigned)__cvta_generic_to_shared(dst_smem);
    asm volatile("cp.async.cg.shared.global.L2::cache_hint [%0], [%1], 16, %2;"
                 :: "r"(saddr), "l"(src), "l"(pol) : "memory");
}
#define CP_COMMIT()  asm volatile("cp.async.commit_group;" ::: "memory")
#define CP_WAIT3()   asm volatile("cp.async.wait_group 3;" ::: "memory")
#define CP_WAIT0()   asm volatile("cp.async.wait_group 0;" ::: "memory")

// Fused butterfly reduction of 4 per-lane partials -> 4 warp sums,
// sigmoid applied once (4 nodes share one MUFU), then broadcast.
// 13 SHFL + 1 MUFU per 4 nodes.
__device__ __forceinline__ void reduce4_sigmoid(float d0, float d1, float d2, float d3,
                                                float& c0, float& c1, float& c2, float& c3,
                                                int lane) {
    const unsigned m = 0xffffffffu;
    float t0 = __shfl_xor_sync(m, d0, 16);
    float t1 = __shfl_xor_sync(m, d1, 16);
    float t2 = __shfl_xor_sync(m, d2, 16);
    float t3 = __shfl_xor_sync(m, d3, 16);
    bool hi16 = (lane & 16) != 0;
    float a = hi16 ? (d2 + t2) : (d0 + t0);
    float b = hi16 ? (d3 + t3) : (d1 + t1);
    float ta = __shfl_xor_sync(m, a, 8);
    float tb = __shfl_xor_sync(m, b, 8);
    bool hi8 = (lane & 8) != 0;
    float c = hi8 ? (b + tb) : (a + ta);
    c += __shfl_xor_sync(m, c, 4);
    c += __shfl_xor_sync(m, c, 2);
    c += __shfl_xor_sync(m, c, 1);
    float s = sigmoidf_(c);
    c0 = __shfl_sync(m, s, 0);
    c1 = __shfl_sync(m, s, 8);
    c2 = __shfl_sync(m, s, 16);
    c3 = __shfl_sync(m, s, 24);
}

__global__ void __launch_bounds__(THREADS, MIN_BLOCKS)
n2g_attention_kernel(const float4* __restrict__ n4,
                     const float4* __restrict__ g4,
                     const void*  __restrict__ nb,
                     float* __restrict__ out,
                     int N, int span) {
    __shared__ float4 sbuf[WARPS_PER_BLOCK][STAGES][GROUP][32];   // 24KB

    const int lane  = threadIdx.x & 31;
    const int w     = threadIdx.x >> 5;
    const int wglob = blockIdx.x * WARPS_PER_BLOCK + w;

    int start = wglob * span;
    if (start >= N) return;
    int end = start + span;
    if (end > N) end = N;

    // int64 detection in-kernel: sorted values in [0,G); reinterpreted as
    // int32, element N-1 is a zero high word iff little-endian int64.
    const int is64 = (((const int*)nb)[N - 1] == 0) ? 1 : 0;
    const unsigned long long pol = mk_policy_ef();

    float4 acc = make_float4(0.f, 0.f, 0.f, 0.f);
    int    cur_b = load_batch(nb, start, is64);
    float4 gv    = __ldg(&g4[cur_b * D4 + lane]);   // cached graph row

    const int cnt     = end - start;
    const int ngroups = cnt >> 2;        // full groups of 4
    int i = start;

    if (ngroups >= STAGES) {
        // prologue: prefetch groups 0..STAGES-1
        #pragma unroll
        for (int s = 0; s < STAGES; ++s) {
            #pragma unroll
            for (int j = 0; j < GROUP; ++j)
                cp16(&sbuf[w][s][j][lane], &n4[(start + s * GROUP + j) * D4 + lane], pol);
            CP_COMMIT();
        }

        // mainloop unrolled x4: ring slot s == k & 3 becomes a constant in
        // each body -> smem addresses fold to immediates, no slot arithmetic.
        #pragma unroll 4
        for (int k = 0; k < ngroups; ++k) {
            const int s    = k & (STAGES - 1);
            const int base = start + (k << 2);

            // monotone indices: if last node of group matches cur_b,
            // the whole group is in the current segment.
            const int b3 = load_batch(nb, base + 3, is64);

            CP_WAIT3();   // group k resident; k+1..k+3 still flying

            if (b3 == cur_b) {
                // ---- fast path: cached gv, no flush checks ----
                // explicit register reuse: one LDS per node row
                const float4 nv0 = sbuf[w][s][0][lane];
                const float4 nv1 = sbuf[w][s][1][lane];
                const float4 nv2 = sbuf[w][s][2][lane];
                const float4 nv3 = sbuf[w][s][3][lane];

                const float d0 = dot4(nv0, gv);
                const float d1 = dot4(nv1, gv);
                const float d2 = dot4(nv2, gv);
                const float d3 = dot4(nv3, gv);

                float c0, c1, c2, c3;
                reduce4_sigmoid(d0, d1, d2, d3, c0, c1, c2, c3, lane);

                acc_add(acc, c0, nv0);
                acc_add(acc, c1, nv1);
                acc_add(acc, c2, nv2);
                acc_add(acc, c3, nv3);
            } else {
                // ---- slow path: segment boundary inside this group ----
                #pragma unroll
                for (int j = 0; j < GROUP; ++j) {
                    const int b = (j == 3) ? b3 : load_batch(nb, base + j, is64);
                    if (b != cur_b) {
                        flush_seg(out, cur_b, lane, acc);
                        acc = make_float4(0.f, 0.f, 0.f, 0.f);
                        cur_b = b;
                        gv = __ldg(&g4[b * D4 + lane]);
                    }
                    const float4 nv = sbuf[w][s][j][lane];
                    float d = dot4(nv, gv);
                    #pragma unroll
                    for (int o = 16; o > 0; o >>= 1)
                        d += __shfl_xor_sync(0xffffffffu, d, o);
                    acc_add(acc, sigmoidf_(d), nv);
                }
            }

            // prefetch group k+STAGES into the slot we just drained
            if (k + STAGES < ngroups) {
                const int nbase = start + ((k + STAGES) << 2);
                #pragma unroll
                for (int j = 0; j < GROUP; ++j)
                    cp16(&sbuf[w][s][j][lane], &n4[(nbase + j) * D4 + lane], pol);
            }
            CP_COMMIT();  // one commit per iter (possibly empty) keeps wait positional
        }
        CP_WAIT0();
        i = start + (ngroups << 2);
    }

    // scalar tail (also the whole range when ngroups < STAGES)
    for (; i < end; ++i) {
        const int b = load_batch(nb, i, is64);
        if (b != cur_b) {
            flush_seg(out, cur_b, lane, acc);
            acc = make_float4(0.f, 0.f, 0.f, 0.f);
            cur_b = b;
            gv = __ldg(&g4[b * D4 + lane]);
        }
        const float4 nv = __ldcs(&n4[i * D4 + lane]);
        float d = dot4(nv, gv);
        #pragma unroll
        for (int o = 16; o > 0; o >>= 1)
            d += __shfl_xor_sync(0xffffffffu, d, o);
        acc_add(acc, sigmoidf_(d), nv);
    }

    flush_seg(out, cur_b, lane, acc);
}

extern "C" void kernel_launch(void* const* d_in, const int* in_sizes, int n_in,
                              void* d_out, int out_size) {
    const float4* n4 = (const float4*)d_in[0];   // n_embedding [N,128] f32
    const float4* g4 = (const float4*)d_in[1];   // g_embedding [G,128] f32
    const void*   nb = d_in[2];                  // n_batch [N] int32 or int64
    float* out = (float*)d_out;                  // [G,128] f32

    const int N = in_sizes[0] / D;

    // zero-init via driver memset (async, graph-capturable, no alloc)
    cudaMemsetAsync(out, 0, (size_t)out_size * sizeof(float), 0);

    int sms = 148;
    cudaDeviceGetAttribute(&sms, cudaDevAttrMultiProcessorCount, 0);

    // balanced persistent grid: every warp gets one contiguous span
    const int blocks      = sms * MIN_BLOCKS;
    const int total_warps = blocks * WARPS_PER_BLOCK;
    int span = (N + total_warps - 1) / total_warps;
    span = (span + GROUP - 1) & ~(GROUP - 1);    // multiple of 4

    n2g_attention_kernel<<<blocks, THREADS>>>(n4, g4, nb, out, N, span);
}